// round 8
// baseline (speedup 1.0000x reference)
#include <cuda_runtime.h>
#include <cuda.h>
#include <cstdint>

// ---------------------------------------------------------------------------
// GroupedLinear: out[t, o] = sum_i X[t, i] * W[g(t), o, i]
// G=8 balanced groups, 2048 tokens/group, in=out=2048, fp32.
//
// R6 analysis: per-SMSP kit time = HMMA(704) + LDSM(256) + cp.async(256) +
// addressing; non-tensor floors stack on the HMMA stream. This round: replace
// per-thread cp.async with bulk TMA (baseline sm_90 PTX, single-thread issue,
// zero addressing math) + mbarrier full/empty pipeline instead of per-kit
// __syncthreads. Math warps now issue only LDSM + HMMA.
// ---------------------------------------------------------------------------

#define NUM_GROUPS 8
#define IN_F       2048
#define OUT_F      2048
#define TOKENS     16384

// Pre-rounded tf32 copies (device-global scratch: allowed)
__device__ float g_xr[(size_t)TOKENS * IN_F];                 // 128 MB
__device__ float g_wr[(size_t)NUM_GROUPS * OUT_F * IN_F];     // 128 MB

constexpr int BM = 128;
constexpr int BN = 128;
constexpr int BK = 32;                       // 32 fp32 = 128 B rows (SW128 atom)
constexpr int THREADS = 128;                 // 4 warps: 2(M) x 2(N), 64x64 each
constexpr int STAGES = 3;
constexpr int KITERS = IN_F / BK;            // 64
constexpr int A_BYTES = BM * BK * 4;         // 16 KB
constexpr int B_BYTES = BN * BK * 4;         // 16 KB
constexpr int STAGE_BYTES = A_BYTES + B_BYTES;    // 32 KB
constexpr int SMEM_CTRL  = 1024;
constexpr int SMEM_TOTAL = SMEM_CTRL + STAGES * STAGE_BYTES;  // 99328 -> 2 CTAs/SM

// mbarrier layout: [full0, empty0, full1, empty1, full2, empty2]
__device__ __forceinline__ uint32_t full_bar(uint32_t sb, int s)  { return sb + s * 16; }
__device__ __forceinline__ uint32_t empty_bar(uint32_t sb, int s) { return sb + s * 16 + 8; }

// ---------------------------------------------------------------------------
// PTX helpers (baseline PTX <= sm_90, no 'a'-gated features)
// ---------------------------------------------------------------------------
__device__ __forceinline__ uint32_t smem_u32(const void* p) {
    uint32_t a;
    asm("{ .reg .u64 t; cvta.to.shared.u64 t, %1; cvt.u32.u64 %0, t; }"
        : "=r"(a) : "l"(p));
    return a;
}

// SW128 swizzle: XOR row bits [9:7] into 16B-chunk bits [6:4]
__device__ __forceinline__ uint32_t swz(uint32_t o) {
    return o ^ ((o >> 3) & 0x70);
}

__device__ __forceinline__ void mbar_init(uint32_t mbar, uint32_t cnt) {
    asm volatile("mbarrier.init.shared.b64 [%0], %1;" :: "r"(mbar), "r"(cnt) : "memory");
}
__device__ __forceinline__ void mbar_expect_tx(uint32_t mbar, uint32_t bytes) {
    asm volatile("mbarrier.arrive.expect_tx.shared.b64 _, [%0], %1;"
                 :: "r"(mbar), "r"(bytes) : "memory");
}
__device__ __forceinline__ void mbar_arrive(uint32_t mbar) {
    asm volatile("mbarrier.arrive.shared.b64 _, [%0];" :: "r"(mbar) : "memory");
}
__device__ __forceinline__ void mbar_wait(uint32_t mbar, uint32_t parity) {
    asm volatile(
        "{\n\t.reg .pred P;\n\t"
        "W_%=:\n\t"
        "mbarrier.try_wait.parity.shared.b64 P, [%0], %1, 0x989680;\n\t"
        "@P bra.uni D_%=;\n\t"
        "bra.uni W_%=;\n\t"
        "D_%=:\n\t}"
        :: "r"(mbar), "r"(parity) : "memory");
}

__device__ __forceinline__ void tma_load_2d(uint32_t smem_dst, const void* tmap,
                                            int cx, int cy, uint32_t mbar) {
    asm volatile(
        "cp.async.bulk.tensor.2d.shared::cta.global.tile.mbarrier::complete_tx::bytes "
        "[%0], [%1, {%2, %3}], [%4];"
        :: "r"(smem_dst), "l"(tmap), "r"(cx), "r"(cy), "r"(mbar) : "memory");
}

__device__ __forceinline__ void ldsm4(uint32_t* r, uint32_t addr) {
    asm volatile("ldmatrix.sync.aligned.m8n8.x4.shared.b16 {%0,%1,%2,%3}, [%4];"
                 : "=r"(r[0]), "=r"(r[1]), "=r"(r[2]), "=r"(r[3]) : "r"(addr));
}

__device__ __forceinline__ void mma_tf32(float* c, const uint32_t* a,
                                         uint32_t b0, uint32_t b1) {
    asm volatile(
        "mma.sync.aligned.m16n8k8.row.col.f32.tf32.tf32.f32 "
        "{%0,%1,%2,%3}, {%4,%5,%6,%7}, {%8,%9}, {%0,%1,%2,%3};"
        : "+f"(c[0]), "+f"(c[1]), "+f"(c[2]), "+f"(c[3])
        : "r"(a[0]), "r"(a[1]), "r"(a[2]), "r"(a[3]), "r"(b0), "r"(b1));
}

// ---------------------------------------------------------------------------
// Pre-pass (single launch, both tensors): fp32 -> RNA-rounded tf32 copy
// ---------------------------------------------------------------------------
constexpr int N4X = (TOKENS * IN_F) / 4;
constexpr int N4W = (NUM_GROUPS * OUT_F * IN_F) / 4;

__global__ void __launch_bounds__(256) round_tf32_kernel(
    const float4* __restrict__ x, const float4* __restrict__ w,
    float4* __restrict__ xr, float4* __restrict__ wr) {
    int i = blockIdx.x * blockDim.x + threadIdx.x;
    const float4* in;
    float4* out;
    int idx;
    if (i < N4X) { in = x; out = xr; idx = i; }
    else         { in = w; out = wr; idx = i - N4X; }
    float4 v = in[idx];
    uint4 o;
    asm("cvt.rna.tf32.f32 %0, %1;" : "=r"(o.x) : "f"(v.x));
    asm("cvt.rna.tf32.f32 %0, %1;" : "=r"(o.y) : "f"(v.y));
    asm("cvt.rna.tf32.f32 %0, %1;" : "=r"(o.z) : "f"(v.z));
    asm("cvt.rna.tf32.f32 %0, %1;" : "=r"(o.w) : "f"(v.w));
    reinterpret_cast<uint4*>(out)[idx] = o;
}

// Fragment loader for one k8 slice (kx = ks*32, applied by XOR)
__device__ __forceinline__ void load_frags(
    uint32_t sA, uint32_t sB, uint32_t kx,
    const uint32_t* a_off, const uint32_t (*b_off)[2],
    uint32_t (*a)[4], uint32_t (*b0)[4], uint32_t (*b1)[4]) {
    #pragma unroll
    for (int i = 0; i < 4; ++i)
        ldsm4(a[i], sA + (a_off[i] ^ kx));
    #pragma unroll
    for (int h = 0; h < 2; ++h) {
        ldsm4(b0[h], sB + (b_off[h][0] ^ kx));
        ldsm4(b1[h], sB + (b_off[h][1] ^ kx));
    }
}

// ---------------------------------------------------------------------------
// Kernel: one 128x128 output tile per CTA, 4 warps, warp tile 64(M) x 64(N).
// TMA-fed 3-stage mbarrier pipeline; math warps issue only LDSM + HMMA.
// ---------------------------------------------------------------------------
__global__ void __launch_bounds__(THREADS, 2)
grouped_gemm_tf32(const __grid_constant__ CUtensorMap tma_a,
                  const __grid_constant__ CUtensorMap tma_b,
                  float* __restrict__ out) {
    extern __shared__ __align__(1024) char smem[];
    const uint32_t sb = smem_u32(smem);
    const int tid  = threadIdx.x;
    const int lane = tid & 31;
    const int wid  = tid >> 5;
    const int warp_m = wid & 1;
    const int warp_n = wid >> 1;

    const int b  = blockIdx.x;
    const int g  = b >> 8;
    const int t  = b & 255;
    const int mt = t >> 4;
    const int nt = t & 15;

    const int row_a = g * (TOKENS / NUM_GROUPS) + mt * BM;   // token row base
    const int row_b = g * OUT_F + nt * BN;                   // weight row base

    if (tid == 0) {
        #pragma unroll
        for (int s = 0; s < STAGES; ++s) {
            mbar_init(full_bar(sb, s), 1);        // producer expect_tx arrival
            mbar_init(empty_bar(sb, s), THREADS); // all consumers arrive
        }
        asm volatile("fence.mbarrier_init.release.cluster;" ::: "memory");
    }
    __syncthreads();

    // Prologue: fill all 3 stages (fresh barriers, no empty-wait needed)
    if (tid == 0) {
        #pragma unroll
        for (int s = 0; s < STAGES; ++s) {
            const uint32_t fb = full_bar(sb, s);
            mbar_expect_tx(fb, STAGE_BYTES);
            const uint32_t sa = sb + SMEM_CTRL + s * STAGE_BYTES;
            tma_load_2d(sa,           &tma_a, s * BK, row_a, fb);
            tma_load_2d(sa + A_BYTES, &tma_b, s * BK, row_b, fb);
        }
    }

    float acc[4][8][4];
    #pragma unroll
    for (int i = 0; i < 4; ++i)
        #pragma unroll
        for (int j = 0; j < 8; ++j)
            #pragma unroll
            for (int r = 0; r < 4; ++r) acc[i][j][r] = 0.0f;

    uint32_t a_off[4];
    #pragma unroll
    for (int i = 0; i < 4; ++i)
        a_off[i] = swz((uint32_t)(
            (warp_m * 64 + i * 16 + (lane & 15)) * 128 + (lane & 16)));
    uint32_t b_off[2][2];
    #pragma unroll
    for (int h = 0; h < 2; ++h) {
        b_off[h][0] = swz((uint32_t)((warp_n * 64 + h * 32 + lane) * 128));
        b_off[h][1] = swz((uint32_t)((warp_n * 64 + h * 32 + lane) * 128 + 16));
    }

    uint32_t a[2][4][4], b0[2][2][4], b1[2][2][4];

    int fph = 0;   // consumer full-wait parity
    int eph = 0;   // producer empty-wait parity
    int s = 0;     // stage cursor

    for (int kit = 0; kit < KITERS; ++kit) {
        mbar_wait(full_bar(sb, s), fph);

        const uint32_t sA = sb + SMEM_CTRL + s * STAGE_BYTES;
        const uint32_t sB = sA + A_BYTES;

        load_frags(sA, sB, 0, a_off, b_off, a[0], b0[0], b1[0]);

        #pragma unroll
        for (int ks = 0; ks < 4; ++ks) {
            const int cur = ks & 1;
            if (ks < 3)
                load_frags(sA, sB, (uint32_t)((ks + 1) * 32), a_off, b_off,
                           a[cur ^ 1], b0[cur ^ 1], b1[cur ^ 1]);
            #pragma unroll
            for (int i = 0; i < 4; ++i)
                #pragma unroll
                for (int j = 0; j < 8; ++j)
                    mma_tf32(acc[i][j], a[cur][i],
                             b0[cur][j >> 2][j & 3], b1[cur][j >> 2][j & 3]);
        }

        // Stage consumed (all LDSM issued; LSU is in-order for smem ops)
        mbar_arrive(empty_bar(sb, s));

        // Producer: refill this stage for kit+3 once all consumers released it
        if (tid == 0 && kit + STAGES < KITERS) {
            mbar_wait(empty_bar(sb, s), eph);
            const uint32_t fb = full_bar(sb, s);
            mbar_expect_tx(fb, STAGE_BYTES);
            tma_load_2d(sA,           &tma_a, (kit + STAGES) * BK, row_a, fb);
            tma_load_2d(sA + A_BYTES, &tma_b, (kit + STAGES) * BK, row_b, fb);
            if (s == STAGES - 1) eph ^= 1;
        }

        if (++s == STAGES) { s = 0; fph ^= 1; }
    }

    // Epilogue: m16n8 C frag: thread holds (r=t/4, c=2*(t%4)) pairs at rows r, r+8
    const int m0 = row_a + warp_m * 64;
    const int n0 = nt * BN + warp_n * 64;
    #pragma unroll
    for (int i = 0; i < 4; ++i) {
        const int r = m0 + i * 16 + (lane >> 2);
        float* p0 = out + (size_t)r * OUT_F + n0 + 2 * (lane & 3);
        float* p1 = p0 + (size_t)8 * OUT_F;
        #pragma unroll
        for (int j = 0; j < 8; ++j) {
            *reinterpret_cast<float2*>(p0 + j * 8) =
                make_float2(acc[i][j][0], acc[i][j][1]);
            *reinterpret_cast<float2*>(p1 + j * 8) =
                make_float2(acc[i][j][2], acc[i][j][3]);
        }
    }
}

// ---------------------------------------------------------------------------
// Host launch
// ---------------------------------------------------------------------------
typedef CUresult (*EncodeTiledFn)(
    CUtensorMap*, CUtensorMapDataType, cuuint32_t, void*,
    const cuuint64_t*, const cuuint64_t*, const cuuint32_t*, const cuuint32_t*,
    CUtensorMapInterleave, CUtensorMapSwizzle, CUtensorMapL2promotion,
    CUtensorMapFloatOOBfill);

extern "C" void kernel_launch(void* const* d_in, const int* in_sizes, int n_in,
                              void* d_out, int out_size) {
    const float* x = (const float*)d_in[0];   // [16384, 2048]
    const float* w = (const float*)d_in[1];   // [8, 2048, 2048]
    float* out = (float*)d_out;               // [16384, 2048]

    float* xr = nullptr;
    float* wr = nullptr;
    cudaGetSymbolAddress((void**)&xr, g_xr);
    cudaGetSymbolAddress((void**)&wr, g_wr);

    static bool attr_set = false;
    if (!attr_set) {
        cudaFuncSetAttribute(grouped_gemm_tf32,
                             cudaFuncAttributeMaxDynamicSharedMemorySize,
                             SMEM_TOTAL);
        attr_set = true;
    }

    // Fused pre-pass: one launch rounds both X and W
    const int total4 = N4X + N4W;
    round_tf32_kernel<<<total4 / 256, 256>>>(
        (const float4*)x, (const float4*)w, (float4*)xr, (float4*)wr);

    // TMA maps: rows = 2048 floats, SW128, box (32, 128)
    void* sym = nullptr;
    cudaDriverEntryPointQueryResult qres;
    cudaGetDriverEntryPointByVersion("cuTensorMapEncodeTiled", &sym, 12000,
                                     cudaEnableDefault, &qres);
    EncodeTiledFn encode = (EncodeTiledFn)sym;

    CUtensorMap mapA, mapB;
    cuuint64_t dims[2]  = {IN_F, TOKENS};     // both tensors are [16384, 2048]
    cuuint64_t strd[1]  = {IN_F * sizeof(float)};
    cuuint32_t box[2]   = {BK, BM};           // 32 x 128 (128 B rows)
    cuuint32_t es[2]    = {1, 1};
    encode(&mapA, CU_TENSOR_MAP_DATA_TYPE_FLOAT32, 2, (void*)xr,
           dims, strd, box, es,
           CU_TENSOR_MAP_INTERLEAVE_NONE, CU_TENSOR_MAP_SWIZZLE_128B,
           CU_TENSOR_MAP_L2_PROMOTION_L2_128B, CU_TENSOR_MAP_FLOAT_OOB_FILL_NONE);
    encode(&mapB, CU_TENSOR_MAP_DATA_TYPE_FLOAT32, 2, (void*)wr,
           dims, strd, box, es,
           CU_TENSOR_MAP_INTERLEAVE_NONE, CU_TENSOR_MAP_SWIZZLE_128B,
           CU_TENSOR_MAP_L2_PROMOTION_L2_128B, CU_TENSOR_MAP_FLOAT_OOB_FILL_NONE);

    const int grid = NUM_GROUPS * (TOKENS / NUM_GROUPS / BM) * (OUT_F / BN); // 2048
    grouped_gemm_tf32<<<grid, THREADS, SMEM_TOTAL>>>(mapA, mapB, out);
}

// round 9
// speedup vs baseline: 1.0469x; 1.0469x over previous
#include <cuda_runtime.h>
#include <cuda.h>
#include <cstdint>

// ---------------------------------------------------------------------------
// GroupedLinear: out[t, o] = sum_i X[t, i] * W[g(t), o, i]
// G=8 balanced groups, 2048 tokens/group, in=out=2048, fp32.
//
// R8 analysis: TMA swap neutral -> binder is tensor-pipe idle from correlated
// stalls at 2 warps/SMSP (64x64 warp tile = 128 acc regs = occupancy wall).
// This round: warp tile 64x32 (acc 64 regs), 8 warps/CTA, <=128 regs
// -> 16 warps/SM (4/SMSP) for 2x latency cover. Single-buffered frags.
// ---------------------------------------------------------------------------

#define NUM_GROUPS 8
#define IN_F       2048
#define OUT_F      2048
#define TOKENS     16384

// Pre-rounded tf32 copies (device-global scratch: allowed)
__device__ float g_xr[(size_t)TOKENS * IN_F];                 // 128 MB
__device__ float g_wr[(size_t)NUM_GROUPS * OUT_F * IN_F];     // 128 MB

constexpr int BM = 128;
constexpr int BN = 128;
constexpr int BK = 32;                       // 32 fp32 = 128 B rows (SW128 atom)
constexpr int THREADS = 256;                 // 8 warps: 2(M) x 4(N), 64x32 each
constexpr int STAGES = 3;
constexpr int KITERS = IN_F / BK;            // 64
constexpr int A_BYTES = BM * BK * 4;         // 16 KB
constexpr int B_BYTES = BN * BK * 4;         // 16 KB
constexpr int STAGE_BYTES = A_BYTES + B_BYTES;    // 32 KB
constexpr int SMEM_CTRL  = 1024;
constexpr int SMEM_TOTAL = SMEM_CTRL + STAGES * STAGE_BYTES;  // 99328 -> 2 CTAs/SM

__device__ __forceinline__ uint32_t full_bar(uint32_t sb, int s)  { return sb + s * 16; }
__device__ __forceinline__ uint32_t empty_bar(uint32_t sb, int s) { return sb + s * 16 + 8; }

// ---------------------------------------------------------------------------
// PTX helpers (baseline PTX <= sm_90, no 'a'-gated features)
// ---------------------------------------------------------------------------
__device__ __forceinline__ uint32_t smem_u32(const void* p) {
    uint32_t a;
    asm("{ .reg .u64 t; cvta.to.shared.u64 t, %1; cvt.u32.u64 %0, t; }"
        : "=r"(a) : "l"(p));
    return a;
}

// SW128 swizzle: XOR row bits [9:7] into 16B-chunk bits [6:4]
__device__ __forceinline__ uint32_t swz(uint32_t o) {
    return o ^ ((o >> 3) & 0x70);
}

__device__ __forceinline__ void mbar_init(uint32_t mbar, uint32_t cnt) {
    asm volatile("mbarrier.init.shared.b64 [%0], %1;" :: "r"(mbar), "r"(cnt) : "memory");
}
__device__ __forceinline__ void mbar_expect_tx(uint32_t mbar, uint32_t bytes) {
    asm volatile("mbarrier.arrive.expect_tx.shared.b64 _, [%0], %1;"
                 :: "r"(mbar), "r"(bytes) : "memory");
}
__device__ __forceinline__ void mbar_arrive(uint32_t mbar) {
    asm volatile("mbarrier.arrive.shared.b64 _, [%0];" :: "r"(mbar) : "memory");
}
__device__ __forceinline__ void mbar_wait(uint32_t mbar, uint32_t parity) {
    asm volatile(
        "{\n\t.reg .pred P;\n\t"
        "W_%=:\n\t"
        "mbarrier.try_wait.parity.shared.b64 P, [%0], %1, 0x989680;\n\t"
        "@P bra.uni D_%=;\n\t"
        "bra.uni W_%=;\n\t"
        "D_%=:\n\t}"
        :: "r"(mbar), "r"(parity) : "memory");
}

__device__ __forceinline__ void tma_load_2d(uint32_t smem_dst, const void* tmap,
                                            int cx, int cy, uint32_t mbar) {
    asm volatile(
        "cp.async.bulk.tensor.2d.shared::cta.global.tile.mbarrier::complete_tx::bytes "
        "[%0], [%1, {%2, %3}], [%4];"
        :: "r"(smem_dst), "l"(tmap), "r"(cx), "r"(cy), "r"(mbar) : "memory");
}

__device__ __forceinline__ void ldsm4(uint32_t* r, uint32_t addr) {
    asm volatile("ldmatrix.sync.aligned.m8n8.x4.shared.b16 {%0,%1,%2,%3}, [%4];"
                 : "=r"(r[0]), "=r"(r[1]), "=r"(r[2]), "=r"(r[3]) : "r"(addr));
}

__device__ __forceinline__ void mma_tf32(float* c, const uint32_t* a,
                                         uint32_t b0, uint32_t b1) {
    asm volatile(
        "mma.sync.aligned.m16n8k8.row.col.f32.tf32.tf32.f32 "
        "{%0,%1,%2,%3}, {%4,%5,%6,%7}, {%8,%9}, {%0,%1,%2,%3};"
        : "+f"(c[0]), "+f"(c[1]), "+f"(c[2]), "+f"(c[3])
        : "r"(a[0]), "r"(a[1]), "r"(a[2]), "r"(a[3]), "r"(b0), "r"(b1));
}

// ---------------------------------------------------------------------------
// Pre-pass (single launch, both tensors): fp32 -> RNA-rounded tf32 copy
// ---------------------------------------------------------------------------
constexpr int N4X = (TOKENS * IN_F) / 4;
constexpr int N4W = (NUM_GROUPS * OUT_F * IN_F) / 4;

__global__ void __launch_bounds__(256) round_tf32_kernel(
    const float4* __restrict__ x, const float4* __restrict__ w,
    float4* __restrict__ xr, float4* __restrict__ wr) {
    int i = blockIdx.x * blockDim.x + threadIdx.x;
    const float4* in;
    float4* out;
    int idx;
    if (i < N4X) { in = x; out = xr; idx = i; }
    else         { in = w; out = wr; idx = i - N4X; }
    float4 v = in[idx];
    uint4 o;
    asm("cvt.rna.tf32.f32 %0, %1;" : "=r"(o.x) : "f"(v.x));
    asm("cvt.rna.tf32.f32 %0, %1;" : "=r"(o.y) : "f"(v.y));
    asm("cvt.rna.tf32.f32 %0, %1;" : "=r"(o.z) : "f"(v.z));
    asm("cvt.rna.tf32.f32 %0, %1;" : "=r"(o.w) : "f"(v.w));
    reinterpret_cast<uint4*>(out)[idx] = o;
}

// ---------------------------------------------------------------------------
// Kernel: one 128x128 output tile per CTA, 8 warps (2Mx4N), warp tile 64x32.
// TMA-fed 3-stage mbarrier pipeline; 16 warps/SM hide LDSM/barrier latency.
// ---------------------------------------------------------------------------
__global__ void __launch_bounds__(THREADS, 2)
grouped_gemm_tf32(const __grid_constant__ CUtensorMap tma_a,
                  const __grid_constant__ CUtensorMap tma_b,
                  float* __restrict__ out) {
    extern __shared__ __align__(1024) char smem[];
    const uint32_t sb = smem_u32(smem);
    const int tid  = threadIdx.x;
    const int lane = tid & 31;
    const int wid  = tid >> 5;
    const int warp_m = wid & 1;    // 0..1 -> 64-row half
    const int warp_n = wid >> 1;   // 0..3 -> 32-col quarter

    const int b  = blockIdx.x;
    const int g  = b >> 8;
    const int t  = b & 255;
    const int mt = t >> 4;
    const int nt = t & 15;

    const int row_a = g * (TOKENS / NUM_GROUPS) + mt * BM;
    const int row_b = g * OUT_F + nt * BN;

    if (tid == 0) {
        #pragma unroll
        for (int s = 0; s < STAGES; ++s) {
            mbar_init(full_bar(sb, s), 1);
            mbar_init(empty_bar(sb, s), THREADS);
        }
        asm volatile("fence.mbarrier_init.release.cluster;" ::: "memory");
    }
    __syncthreads();

    // Prologue: fill all 3 stages
    if (tid == 0) {
        #pragma unroll
        for (int s = 0; s < STAGES; ++s) {
            const uint32_t fb = full_bar(sb, s);
            mbar_expect_tx(fb, STAGE_BYTES);
            const uint32_t sa = sb + SMEM_CTRL + s * STAGE_BYTES;
            tma_load_2d(sa,           &tma_a, s * BK, row_a, fb);
            tma_load_2d(sa + A_BYTES, &tma_b, s * BK, row_b, fb);
        }
    }

    float acc[4][4][4];
    #pragma unroll
    for (int i = 0; i < 4; ++i)
        #pragma unroll
        for (int j = 0; j < 4; ++j)
            #pragma unroll
            for (int r = 0; r < 4; ++r) acc[i][j][r] = 0.0f;

    uint32_t a_off[4];
    #pragma unroll
    for (int i = 0; i < 4; ++i)
        a_off[i] = swz((uint32_t)(
            (warp_m * 64 + i * 16 + (lane & 15)) * 128 + (lane & 16)));
    const uint32_t b_off0 = swz((uint32_t)((warp_n * 32 + lane) * 128));
    const uint32_t b_off1 = swz((uint32_t)((warp_n * 32 + lane) * 128 + 16));

    int fph = 0;   // consumer full-wait parity
    int eph = 0;   // producer empty-wait parity
    int s = 0;     // stage cursor

    for (int kit = 0; kit < KITERS; ++kit) {
        mbar_wait(full_bar(sb, s), fph);

        const uint32_t sA = sb + SMEM_CTRL + s * STAGE_BYTES;
        const uint32_t sB = sA + A_BYTES;

        #pragma unroll
        for (int ks = 0; ks < 4; ++ks) {
            const uint32_t kx = (uint32_t)(ks * 32);

            uint32_t a[4][4];
            #pragma unroll
            for (int i = 0; i < 4; ++i)
                ldsm4(a[i], sA + (a_off[i] ^ kx));
            uint32_t b0[4], b1[4];
            ldsm4(b0, sB + (b_off0 ^ kx));
            ldsm4(b1, sB + (b_off1 ^ kx));

            #pragma unroll
            for (int i = 0; i < 4; ++i)
                #pragma unroll
                for (int j = 0; j < 4; ++j)
                    mma_tf32(acc[i][j], a[i], b0[j], b1[j]);
        }

        mbar_arrive(empty_bar(sb, s));

        // Producer: refill this stage for kit+3 once all consumers released it
        if (tid == 0 && kit + STAGES < KITERS) {
            mbar_wait(empty_bar(sb, s), eph);
            const uint32_t fb = full_bar(sb, s);
            mbar_expect_tx(fb, STAGE_BYTES);
            tma_load_2d(sA,           &tma_a, (kit + STAGES) * BK, row_a, fb);
            tma_load_2d(sA + A_BYTES, &tma_b, (kit + STAGES) * BK, row_b, fb);
            if (s == STAGES - 1) eph ^= 1;
        }

        if (++s == STAGES) { s = 0; fph ^= 1; }
    }

    // Epilogue: m16n8 C frag: thread holds (r=t/4, c=2*(t%4)) pairs at rows r, r+8
    const int m0 = row_a + warp_m * 64;
    const int n0 = nt * BN + warp_n * 32;
    #pragma unroll
    for (int i = 0; i < 4; ++i) {
        const int r = m0 + i * 16 + (lane >> 2);
        float* p0 = out + (size_t)r * OUT_F + n0 + 2 * (lane & 3);
        float* p1 = p0 + (size_t)8 * OUT_F;
        #pragma unroll
        for (int j = 0; j < 4; ++j) {
            *reinterpret_cast<float2*>(p0 + j * 8) =
                make_float2(acc[i][j][0], acc[i][j][1]);
            *reinterpret_cast<float2*>(p1 + j * 8) =
                make_float2(acc[i][j][2], acc[i][j][3]);
        }
    }
}

// ---------------------------------------------------------------------------
// Host launch
// ---------------------------------------------------------------------------
typedef CUresult (*EncodeTiledFn)(
    CUtensorMap*, CUtensorMapDataType, cuuint32_t, void*,
    const cuuint64_t*, const cuuint64_t*, const cuuint32_t*, const cuuint32_t*,
    CUtensorMapInterleave, CUtensorMapSwizzle, CUtensorMapL2promotion,
    CUtensorMapFloatOOBfill);

extern "C" void kernel_launch(void* const* d_in, const int* in_sizes, int n_in,
                              void* d_out, int out_size) {
    const float* x = (const float*)d_in[0];   // [16384, 2048]
    const float* w = (const float*)d_in[1];   // [8, 2048, 2048]
    float* out = (float*)d_out;               // [16384, 2048]

    float* xr = nullptr;
    float* wr = nullptr;
    cudaGetSymbolAddress((void**)&xr, g_xr);
    cudaGetSymbolAddress((void**)&wr, g_wr);

    static bool attr_set = false;
    if (!attr_set) {
        cudaFuncSetAttribute(grouped_gemm_tf32,
                             cudaFuncAttributeMaxDynamicSharedMemorySize,
                             SMEM_TOTAL);
        attr_set = true;
    }

    // Fused pre-pass: one launch rounds both X and W
    const int total4 = N4X + N4W;
    round_tf32_kernel<<<total4 / 256, 256>>>(
        (const float4*)x, (const float4*)w, (float4*)xr, (float4*)wr);

    // TMA maps: rows = 2048 floats, SW128, box (32, 128)
    void* sym = nullptr;
    cudaDriverEntryPointQueryResult qres;
    cudaGetDriverEntryPointByVersion("cuTensorMapEncodeTiled", &sym, 12000,
                                     cudaEnableDefault, &qres);
    EncodeTiledFn encode = (EncodeTiledFn)sym;

    CUtensorMap mapA, mapB;
    cuuint64_t dims[2]  = {IN_F, TOKENS};     // both tensors are [16384, 2048]
    cuuint64_t strd[1]  = {IN_F * sizeof(float)};
    cuuint32_t box[2]   = {BK, BM};           // 32 x 128 (128 B rows)
    cuuint32_t es[2]    = {1, 1};
    encode(&mapA, CU_TENSOR_MAP_DATA_TYPE_FLOAT32, 2, (void*)xr,
           dims, strd, box, es,
           CU_TENSOR_MAP_INTERLEAVE_NONE, CU_TENSOR_MAP_SWIZZLE_128B,
           CU_TENSOR_MAP_L2_PROMOTION_L2_128B, CU_TENSOR_MAP_FLOAT_OOB_FILL_NONE);
    encode(&mapB, CU_TENSOR_MAP_DATA_TYPE_FLOAT32, 2, (void*)wr,
           dims, strd, box, es,
           CU_TENSOR_MAP_INTERLEAVE_NONE, CU_TENSOR_MAP_SWIZZLE_128B,
           CU_TENSOR_MAP_L2_PROMOTION_L2_128B, CU_TENSOR_MAP_FLOAT_OOB_FILL_NONE);

    const int grid = NUM_GROUPS * (TOKENS / NUM_GROUPS / BM) * (OUT_F / BN); // 2048
    grouped_gemm_tf32<<<grid, THREADS, SMEM_TOTAL>>>(mapA, mapB, out);
}

// round 11
// speedup vs baseline: 1.0735x; 1.0255x over previous
#include <cuda_runtime.h>
#include <cuda.h>
#include <cstdint>

// ---------------------------------------------------------------------------
// GroupedLinear: out[t, o] = sum_i X[t, i] * W[g(t), o, i]
// G=8 balanced groups, 2048 tokens/group, in=out=2048, fp32.
//
// R9 analysis: tensor-busy is a constant 452us; dur = 452/tensor_pct.
// Crossbar and tensor co-bind but overlap poorly because ALL asm was
// volatile (no LDSM/MMA interleave) and frags were single-buffered.
// This round: non-volatile MMA + explicit ks frag double-buffering +
// per-warp (not per-thread) empty-barrier arrival.
// ---------------------------------------------------------------------------

#define NUM_GROUPS 8
#define IN_F       2048
#define OUT_F      2048
#define TOKENS     16384

// Pre-rounded tf32 copies (device-global scratch: allowed)
__device__ float g_xr[(size_t)TOKENS * IN_F];                 // 128 MB
__device__ float g_wr[(size_t)NUM_GROUPS * OUT_F * IN_F];     // 128 MB

constexpr int BM = 128;
constexpr int BN = 128;
constexpr int BK = 32;                       // 32 fp32 = 128 B rows (SW128 atom)
constexpr int THREADS = 256;                 // 8 warps: 2(M) x 4(N), 64x32 each
constexpr int WARPS   = THREADS / 32;
constexpr int STAGES = 3;
constexpr int KITERS = IN_F / BK;            // 64
constexpr int A_BYTES = BM * BK * 4;         // 16 KB
constexpr int B_BYTES = BN * BK * 4;         // 16 KB
constexpr int STAGE_BYTES = A_BYTES + B_BYTES;    // 32 KB
constexpr int SMEM_CTRL  = 1024;
constexpr int SMEM_TOTAL = SMEM_CTRL + STAGES * STAGE_BYTES;  // 99328 -> 2 CTAs/SM

__device__ __forceinline__ uint32_t full_bar(uint32_t sb, int s)  { return sb + s * 16; }
__device__ __forceinline__ uint32_t empty_bar(uint32_t sb, int s) { return sb + s * 16 + 8; }

// ---------------------------------------------------------------------------
// PTX helpers (baseline PTX <= sm_90, no 'a'-gated features)
// ---------------------------------------------------------------------------
__device__ __forceinline__ uint32_t smem_u32(const void* p) {
    uint32_t a;
    asm("{ .reg .u64 t; cvta.to.shared.u64 t, %1; cvt.u32.u64 %0, t; }"
        : "=r"(a) : "l"(p));
    return a;
}

// SW128 swizzle: XOR row bits [9:7] into 16B-chunk bits [6:4]
__device__ __forceinline__ uint32_t swz(uint32_t o) {
    return o ^ ((o >> 3) & 0x70);
}

__device__ __forceinline__ void mbar_init(uint32_t mbar, uint32_t cnt) {
    asm volatile("mbarrier.init.shared.b64 [%0], %1;" :: "r"(mbar), "r"(cnt) : "memory");
}
__device__ __forceinline__ void mbar_expect_tx(uint32_t mbar, uint32_t bytes) {
    asm volatile("mbarrier.arrive.expect_tx.shared.b64 _, [%0], %1;"
                 :: "r"(mbar), "r"(bytes) : "memory");
}
__device__ __forceinline__ void mbar_arrive(uint32_t mbar) {
    asm volatile("mbarrier.arrive.shared.b64 _, [%0];" :: "r"(mbar) : "memory");
}
__device__ __forceinline__ void mbar_wait(uint32_t mbar, uint32_t parity) {
    asm volatile(
        "{\n\t.reg .pred P;\n\t"
        "W_%=:\n\t"
        "mbarrier.try_wait.parity.shared.b64 P, [%0], %1, 0x989680;\n\t"
        "@P bra.uni D_%=;\n\t"
        "bra.uni W_%=;\n\t"
        "D_%=:\n\t}"
        :: "r"(mbar), "r"(parity) : "memory");
}

__device__ __forceinline__ void tma_load_2d(uint32_t smem_dst, const void* tmap,
                                            int cx, int cy, uint32_t mbar) {
    asm volatile(
        "cp.async.bulk.tensor.2d.shared::cta.global.tile.mbarrier::complete_tx::bytes "
        "[%0], [%1, {%2, %3}], [%4];"
        :: "r"(smem_dst), "l"(tmap), "r"(cx), "r"(cy), "r"(mbar) : "memory");
}

// Volatile: must stay ordered after the mbar_wait that publishes the stage.
__device__ __forceinline__ void ldsm4(uint32_t* r, uint32_t addr) {
    asm volatile("ldmatrix.sync.aligned.m8n8.x4.shared.b16 {%0,%1,%2,%3}, [%4];"
                 : "=r"(r[0]), "=r"(r[1]), "=r"(r[2]), "=r"(r[3]) : "r"(addr));
}

// NON-volatile: pure register math; lets ptxas interleave MMAs with the
// next slice's LDSMs instead of serializing burst-by-burst.
__device__ __forceinline__ void mma_tf32(float* c, const uint32_t* a,
                                         uint32_t b0, uint32_t b1) {
    asm("mma.sync.aligned.m16n8k8.row.col.f32.tf32.tf32.f32 "
        "{%0,%1,%2,%3}, {%4,%5,%6,%7}, {%8,%9}, {%0,%1,%2,%3};"
        : "+f"(c[0]), "+f"(c[1]), "+f"(c[2]), "+f"(c[3])
        : "r"(a[0]), "r"(a[1]), "r"(a[2]), "r"(a[3]), "r"(b0), "r"(b1));
}

// ---------------------------------------------------------------------------
// Pre-pass (single launch, both tensors): fp32 -> RNA-rounded tf32 copy
// ---------------------------------------------------------------------------
constexpr int N4X = (TOKENS * IN_F) / 4;
constexpr int N4W = (NUM_GROUPS * OUT_F * IN_F) / 4;

__global__ void __launch_bounds__(256) round_tf32_kernel(
    const float4* __restrict__ x, const float4* __restrict__ w,
    float4* __restrict__ xr, float4* __restrict__ wr) {
    int i = blockIdx.x * blockDim.x + threadIdx.x;
    const float4* in;
    float4* out;
    int idx;
    if (i < N4X) { in = x; out = xr; idx = i; }
    else         { in = w; out = wr; idx = i - N4X; }
    float4 v = in[idx];
    uint4 o;
    asm("cvt.rna.tf32.f32 %0, %1;" : "=r"(o.x) : "f"(v.x));
    asm("cvt.rna.tf32.f32 %0, %1;" : "=r"(o.y) : "f"(v.y));
    asm("cvt.rna.tf32.f32 %0, %1;" : "=r"(o.z) : "f"(v.z));
    asm("cvt.rna.tf32.f32 %0, %1;" : "=r"(o.w) : "f"(v.w));
    reinterpret_cast<uint4*>(out)[idx] = o;
}

// ---------------------------------------------------------------------------
// Kernel: one 128x128 tile per CTA, 8 warps (2Mx4N), warp tile 64x32.
// TMA 3-stage mbarrier pipeline; ks-level register double-buffered frags.
// ---------------------------------------------------------------------------
__global__ void __launch_bounds__(THREADS, 2)
grouped_gemm_tf32(const __grid_constant__ CUtensorMap tma_a,
                  const __grid_constant__ CUtensorMap tma_b,
                  float* __restrict__ out) {
    extern __shared__ __align__(1024) char smem[];
    const uint32_t sb = smem_u32(smem);
    const int tid  = threadIdx.x;
    const int lane = tid & 31;
    const int wid  = tid >> 5;
    const int warp_m = wid & 1;    // 0..1 -> 64-row half
    const int warp_n = wid >> 1;   // 0..3 -> 32-col quarter

    const int b  = blockIdx.x;
    const int g  = b >> 8;
    const int t  = b & 255;
    const int mt = t >> 4;
    const int nt = t & 15;

    const int row_a = g * (TOKENS / NUM_GROUPS) + mt * BM;
    const int row_b = g * OUT_F + nt * BN;

    if (tid == 0) {
        #pragma unroll
        for (int s = 0; s < STAGES; ++s) {
            mbar_init(full_bar(sb, s), 1);
            mbar_init(empty_bar(sb, s), WARPS);   // one arrive per warp
        }
        asm volatile("fence.mbarrier_init.release.cluster;" ::: "memory");
    }
    __syncthreads();

    // Prologue: fill all 3 stages
    if (tid == 0) {
        #pragma unroll
        for (int s = 0; s < STAGES; ++s) {
            const uint32_t fb = full_bar(sb, s);
            mbar_expect_tx(fb, STAGE_BYTES);
            const uint32_t sa = sb + SMEM_CTRL + s * STAGE_BYTES;
            tma_load_2d(sa,           &tma_a, s * BK, row_a, fb);
            tma_load_2d(sa + A_BYTES, &tma_b, s * BK, row_b, fb);
        }
    }

    float acc[4][4][4];
    #pragma unroll
    for (int i = 0; i < 4; ++i)
        #pragma unroll
        for (int j = 0; j < 4; ++j)
            #pragma unroll
            for (int r = 0; r < 4; ++r) acc[i][j][r] = 0.0f;

    uint32_t a_off[4];
    #pragma unroll
    for (int i = 0; i < 4; ++i)
        a_off[i] = swz((uint32_t)(
            (warp_m * 64 + i * 16 + (lane & 15)) * 128 + (lane & 16)));
    const uint32_t b_off0 = swz((uint32_t)((warp_n * 32 + lane) * 128));
    const uint32_t b_off1 = swz((uint32_t)((warp_n * 32 + lane) * 128 + 16));

    // Double-buffered fragments (2 x 24 regs)
    uint32_t a[2][4][4], b0[2][4], b1[2][4];

    int fph = 0;   // consumer full-wait parity
    int eph = 0;   // producer empty-wait parity
    int s = 0;     // stage cursor

    for (int kit = 0; kit < KITERS; ++kit) {
        mbar_wait(full_bar(sb, s), fph);

        const uint32_t sA = sb + SMEM_CTRL + s * STAGE_BYTES;
        const uint32_t sB = sA + A_BYTES;

        // ks0 frags
        #pragma unroll
        for (int i = 0; i < 4; ++i)
            ldsm4(a[0][i], sA + (a_off[i] ^ 0u));
        ldsm4(b0[0], sB + (b_off0 ^ 0u));
        ldsm4(b1[0], sB + (b_off1 ^ 0u));

        #pragma unroll
        for (int ks = 0; ks < 4; ++ks) {
            const int cur = ks & 1;
            if (ks < 3) {
                const uint32_t kx = (uint32_t)((ks + 1) * 32);
                #pragma unroll
                for (int i = 0; i < 4; ++i)
                    ldsm4(a[cur ^ 1][i], sA + (a_off[i] ^ kx));
                ldsm4(b0[cur ^ 1], sB + (b_off0 ^ kx));
                ldsm4(b1[cur ^ 1], sB + (b_off1 ^ kx));
            }
            #pragma unroll
            for (int i = 0; i < 4; ++i)
                #pragma unroll
                for (int j = 0; j < 4; ++j)
                    mma_tf32(acc[i][j], a[cur][i], b0[cur][j], b1[cur][j]);
        }

        // Stage consumed: one arrive per warp (all frag regs already written,
        // so every LDSM against this stage has completed).
        if (lane == 0) mbar_arrive(empty_bar(sb, s));

        // Producer: refill this stage for kit+3 once all warps released it
        if (tid == 0 && kit + STAGES < KITERS) {
            mbar_wait(empty_bar(sb, s), eph);
            const uint32_t fb = full_bar(sb, s);
            mbar_expect_tx(fb, STAGE_BYTES);
            tma_load_2d(sA,           &tma_a, (kit + STAGES) * BK, row_a, fb);
            tma_load_2d(sA + A_BYTES, &tma_b, (kit + STAGES) * BK, row_b, fb);
            if (s == STAGES - 1) eph ^= 1;
        }

        if (++s == STAGES) { s = 0; fph ^= 1; }
    }

    // Epilogue: m16n8 C frag: thread holds (r=t/4, c=2*(t%4)) pairs at rows r, r+8
    const int m0 = row_a + warp_m * 64;
    const int n0 = nt * BN + warp_n * 32;
    #pragma unroll
    for (int i = 0; i < 4; ++i) {
        const int r = m0 + i * 16 + (lane >> 2);
        float* p0 = out + (size_t)r * OUT_F + n0 + 2 * (lane & 3);
        float* p1 = p0 + (size_t)8 * OUT_F;
        #pragma unroll
        for (int j = 0; j < 4; ++j) {
            *reinterpret_cast<float2*>(p0 + j * 8) =
                make_float2(acc[i][j][0], acc[i][j][1]);
            *reinterpret_cast<float2*>(p1 + j * 8) =
                make_float2(acc[i][j][2], acc[i][j][3]);
        }
    }
}

// ---------------------------------------------------------------------------
// Host launch
// ---------------------------------------------------------------------------
typedef CUresult (*EncodeTiledFn)(
    CUtensorMap*, CUtensorMapDataType, cuuint32_t, void*,
    const cuuint64_t*, const cuuint64_t*, const cuuint32_t*, const cuuint32_t*,
    CUtensorMapInterleave, CUtensorMapSwizzle, CUtensorMapL2promotion,
    CUtensorMapFloatOOBfill);

extern "C" void kernel_launch(void* const* d_in, const int* in_sizes, int n_in,
                              void* d_out, int out_size) {
    const float* x = (const float*)d_in[0];   // [16384, 2048]
    const float* w = (const float*)d_in[1];   // [8, 2048, 2048]
    float* out = (float*)d_out;               // [16384, 2048]

    float* xr = nullptr;
    float* wr = nullptr;
    cudaGetSymbolAddress((void**)&xr, g_xr);
    cudaGetSymbolAddress((void**)&wr, g_wr);

    static bool attr_set = false;
    if (!attr_set) {
        cudaFuncSetAttribute(grouped_gemm_tf32,
                             cudaFuncAttributeMaxDynamicSharedMemorySize,
                             SMEM_TOTAL);
        attr_set = true;
    }

    // Fused pre-pass: one launch rounds both X and W
    const int total4 = N4X + N4W;
    round_tf32_kernel<<<total4 / 256, 256>>>(
        (const float4*)x, (const float4*)w, (float4*)xr, (float4*)wr);

    // TMA maps: rows = 2048 floats, SW128, box (32, 128)
    void* sym = nullptr;
    cudaDriverEntryPointQueryResult qres;
    cudaGetDriverEntryPointByVersion("cuTensorMapEncodeTiled", &sym, 12000,
                                     cudaEnableDefault, &qres);
    EncodeTiledFn encode = (EncodeTiledFn)sym;

    CUtensorMap mapA, mapB;
    cuuint64_t dims[2]  = {IN_F, TOKENS};     // both tensors are [16384, 2048]
    cuuint64_t strd[1]  = {IN_F * sizeof(float)};
    cuuint32_t box[2]   = {BK, BM};           // 32 x 128 (128 B rows)
    cuuint32_t es[2]    = {1, 1};
    encode(&mapA, CU_TENSOR_MAP_DATA_TYPE_FLOAT32, 2, (void*)xr,
           dims, strd, box, es,
           CU_TENSOR_MAP_INTERLEAVE_NONE, CU_TENSOR_MAP_SWIZZLE_128B,
           CU_TENSOR_MAP_L2_PROMOTION_L2_128B, CU_TENSOR_MAP_FLOAT_OOB_FILL_NONE);
    encode(&mapB, CU_TENSOR_MAP_DATA_TYPE_FLOAT32, 2, (void*)wr,
           dims, strd, box, es,
           CU_TENSOR_MAP_INTERLEAVE_NONE, CU_TENSOR_MAP_SWIZZLE_128B,
           CU_TENSOR_MAP_L2_PROMOTION_L2_128B, CU_TENSOR_MAP_FLOAT_OOB_FILL_NONE);

    const int grid = NUM_GROUPS * (TOKENS / NUM_GROUPS / BM) * (OUT_F / BN); // 2048
    grouped_gemm_tf32<<<grid, THREADS, SMEM_TOTAL>>>(mapA, mapB, out);
}